// round 14
// baseline (speedup 1.0000x reference)
#include <cuda_runtime.h>
#include <cuda_fp16.h>
#include <math.h>
#include <float.h>
#include <stdint.h>

#define BB 4
#define NN 2048
#define KNN 20
#define TD 64
#define GD 128
#define OBJ 200
#define IMGD 224
#define HW (IMGD*IMGD)
#define EPSF 1e-5f

// XLA:GPU f32 division (fdiv -> div.full.f32) — correctness-critical for grid placement
__device__ __forceinline__ float divfull(float a, float b)
{
    float r;
    asm("div.full.f32 %0, %1, %2;" : "=f"(r) : "f"(a), "f"(b));
    return r;
}

__device__ __forceinline__ unsigned packh2(float a, float b)
{
    __half2 h = __floats2half2_rn(a, b);
    return *reinterpret_cast<unsigned*>(&h);
}

__device__ float  g_x[BB*NN*TD];
__device__ int    g_idx[BB*NN*KNN];
__device__ float  g_A[BB*NN*GD];
__device__ float  g_C[BB*NN*GD];
__device__ double g_stats[BB*4*2];
__device__ float  g_f2[BB*NN*GD];
__device__ float  g_bp[BB*8];
__device__ float  g_res[BB*GD*HW];
__device__ float  g_h1 [BB*GD*HW];
__device__ __half g_w1h[1152*GD];     // chunked [c][oc][16k] fp16, BN folded
__device__ __half g_w2h[1152*GD];
__device__ float  g_b1[GD];
__device__ float  g_b2[GD];
__device__ float  g_wgT[128*GD];
__device__ float  g_wpT[GD*GD];
__device__ float  g_wc[3*GD];
__device__ float  g_bc[3];

// ---------------- merged zero + weight prep ----------------
__global__ void k_init(const float* __restrict__ W1, const float* __restrict__ bn1g,
                       const float* __restrict__ bn1b, const float* __restrict__ bn1m,
                       const float* __restrict__ bn1v,
                       const float* __restrict__ W2, const float* __restrict__ bn2g,
                       const float* __restrict__ bn2b, const float* __restrict__ bn2m,
                       const float* __restrict__ bn2v,
                       const float* __restrict__ Wg, const float* __restrict__ Wp,
                       const float* __restrict__ Wimgc, const float* __restrict__ bimgc,
                       const float* __restrict__ Wimg, const float* __restrict__ bimg)
{
    int bid = blockIdx.x, t = threadIdx.x;
    size_t i = (size_t)bid*blockDim.x + t;

    size_t n4 = ((size_t)BB*GD*HW)/4;
    float4* r4 = (float4*)g_res;
    float4 z = make_float4(0.f,0.f,0.f,0.f);
    for (size_t j = i; j < n4; j += (size_t)gridDim.x*blockDim.x) r4[j] = z;
    if (i < BB*4*2) ((double*)g_stats)[i] = 0.0;

    if (bid < 1152) {
        int variant = (bid >= 576);
        int e = (variant ? bid - 576 : bid)*256 + t;
        const float* W  = variant ? W2   : W1;
        const float* ga = variant ? bn2g : bn1g;
        const float* be = variant ? bn2b : bn1b;
        const float* mm = variant ? bn2m : bn1m;
        const float* vv = variant ? bn2v : bn1v;
        __half* wh  = variant ? g_w2h : g_w1h;
        float* bias = variant ? g_b2  : g_b1;
        if (e < 128) {
            float sc = ga[e] * rsqrtf(__fadd_rn(vv[e], EPSF));
            bias[e] = __fsub_rn(be[e], __fmul_rn(mm[e], sc));
        }
        if (e < 1152*128) {
            int oc = e / 1152;
            int k  = e - oc*1152;
            float sc = ga[oc] * rsqrtf(__fadd_rn(vv[oc], EPSF));
            int c  = k >> 4, kk = k & 15;
            wh[((size_t)c*128 + oc)*16 + kk] = __float2half_rn(__fmul_rn(W[e], sc));
        }
    } else if (bid < 1216) {
        int e = (bid - 1152)*256 + t;
        int o = e >> 7, c = e & 127;
        g_wgT[c*128 + o] = Wg[e];
        g_wpT[c*128 + o] = Wp[e];
    } else if (bid == 1216) {
        for (int idx = t; idx < 384; idx += 256) {
            int j = idx / 128, c = idx - j*128;
            float s = 0.f;
            for (int o = 0; o < 128; o++) s += Wimg[j*128+o] * Wimgc[o*128+c];
            g_wc[idx] = s;
        }
        if (t < 3) {
            float s = bimg[t];
            for (int o = 0; o < 128; o++) s += Wimg[t*128+o] * bimgc[o];
            g_bc[t] = s;
        }
    }
}

__global__ void k_x(const float* __restrict__ opc, const float* __restrict__ W_in,
                    const float* __restrict__ b_in)
{
    int bn = blockIdx.x, c = threadIdx.x;   // 64
    __shared__ float p[3];
    if (c < 3) p[c] = opc[(size_t)bn*3 + c];
    __syncthreads();
    float v = __fadd_rn(__fadd_rn(__fadd_rn(__fmul_rn(p[0], W_in[c*3+0]),
                        __fmul_rn(p[1], W_in[c*3+1])), __fmul_rn(p[2], W_in[c*3+2])), b_in[c]);
    g_x[(size_t)bn*TD + c] = v;
}

__global__ __launch_bounds__(128) void k_knn(const float* __restrict__ opc)
{
    __shared__ float sbuf[4*NN];
    float* sx  = sbuf;
    float* sy  = sbuf + NN;
    float* sz  = sbuf + 2*NN;
    float* ssq = sbuf + 3*NN;

    int b  = blockIdx.x >> 9;
    int nb = (blockIdx.x & 511) * 4;
    int t = threadIdx.x, w = t >> 5, lane = t & 31;
    const float* pcb = opc + (size_t)b*NN*3;
    for (int i = t; i < NN; i += 128) {
        float x = pcb[i*3+0], y = pcb[i*3+1], zz = pcb[i*3+2];
        sx[i] = x; sy[i] = y; sz[i] = zz;
        float s01 = __fadd_rn(__fmul_rn(x,x), __fmul_rn(y,y));
        ssq[i] = __fadd_rn(s01, __fmul_rn(zz,zz));
    }
    __syncthreads();

    int n = nb + w;
    float qx = sx[n], qy = sy[n], qz = sz[n], qsq = ssq[n];

    float d[KNN]; int id[KNN];
    #pragma unroll
    for (int j = 0; j < KNN; j++){ d[j] = FLT_MAX; id[j] = 0x7fffffff; }
    float worst = FLT_MAX; int wpos = 0;

    for (int m = lane; m < NN; m += 32) {
        float dot  = __fadd_rn(__fadd_rn(__fmul_rn(qx, sx[m]), __fmul_rn(qy, sy[m])),
                               __fmul_rn(qz, sz[m]));
        float dist = __fsub_rn(__fadd_rn(qsq, ssq[m]), __fmul_rn(2.0f, dot));
        if (dist < worst) {
            #pragma unroll
            for (int j = 0; j < KNN; j++) if (j == wpos){ d[j] = dist; id[j] = m; }
            worst = -FLT_MAX;
            #pragma unroll
            for (int j = 0; j < KNN; j++) if (d[j] > worst){ worst = d[j]; wpos = j; }
        }
    }
    __syncthreads();

    float* cd  = sbuf;
    int*   cid = (int*)(sbuf + 2560);
    int base = w*640 + lane*KNN;
    #pragma unroll
    for (int j = 0; j < KNN; j++){ cd[base+j] = d[j]; cid[base+j] = id[j]; }
    __syncwarp();

    int* out = g_idx + ((size_t)(b*NN + n))*KNN;
    for (int r = 0; r < KNN; r++) {
        float mv = FLT_MAX; int mp = 0; int midx = 0x7fffffff;
        #pragma unroll
        for (int j = 0; j < KNN; j++) {
            float v = cd[w*640 + lane*KNN + j];
            int   ii = cid[w*640 + lane*KNN + j];
            if (v < mv || (v == mv && ii < midx)) { mv = v; midx = ii; mp = lane*KNN + j; }
        }
        for (int off = 16; off; off >>= 1) {
            float ov = __shfl_down_sync(0xffffffffu, mv, off);
            int   oi = __shfl_down_sync(0xffffffffu, midx, off);
            int   op = __shfl_down_sync(0xffffffffu, mp, off);
            if (ov < mv || (ov == mv && oi < midx)) { mv = ov; midx = oi; mp = op; }
        }
        mp = __shfl_sync(0xffffffffu, mp, 0);
        if (lane == 0) { out[r] = cid[w*640 + mp]; cd[w*640 + mp] = FLT_MAX; }
        __syncwarp();
    }
}

__global__ void k_projAC()
{
    int bn = blockIdx.x, o = threadIdx.x;  // 128
    __shared__ float xs[TD];
    if (o < TD) xs[o] = g_x[(size_t)bn*TD + o];
    __syncthreads();
    float a = 0.f, c2 = 0.f;
    #pragma unroll 8
    for (int c = 0; c < TD; c++) {
        float xv = xs[c];
        a  += xv * g_wgT[c*128 + o];
        c2 += xv * g_wgT[(c+TD)*128 + o];
    }
    g_A[(size_t)bn*GD + o] = a;
    g_C[(size_t)bn*GD + o] = c2 - a;
}

__global__ void k_stats()
{
    int bn = blockIdx.x, b = bn >> 11, o = threadIdx.x;
    __shared__ int sidx[KNN];
    if (o < KNN) sidx[o] = g_idx[(size_t)bn*KNN + o];
    __syncthreads();
    float c = g_C[(size_t)bn*GD + o];
    const float* Ab = g_A + (size_t)b*NN*GD;
    float s1 = 0.f, s2 = 0.f;
    #pragma unroll
    for (int k = 0; k < KNN; k++) {
        float v = Ab[(size_t)sidx[k]*GD + o] + c;
        s1 += v; s2 += v*v;
    }
    for (int off = 16; off; off >>= 1) {
        s1 += __shfl_down_sync(0xffffffffu, s1, off);
        s2 += __shfl_down_sync(0xffffffffu, s2, off);
    }
    if ((o & 31) == 0) {
        int g = o >> 5;
        atomicAdd(&g_stats[(b*4+g)*2+0], (double)s1);
        atomicAdd(&g_stats[(b*4+g)*2+1], (double)s2);
    }
}

// finstats folded in: each block recomputes mu/iv from g_stats (bit-identical math)
__global__ void k_f2(const float* __restrict__ gn_g, const float* __restrict__ gn_b,
                     const float* __restrict__ b_proj)
{
    __shared__ float fsh[16][GD];
    __shared__ int   sidx[16*KNN];
    __shared__ float smu[4], siv[4];
    int bn0 = blockIdx.x * 16;
    int b   = bn0 >> 11;
    int o   = threadIdx.x;
    int g   = o >> 5;
    if (o < 4) {
        double cnt = (double)NN * KNN * 32.0;
        double mu = g_stats[(b*4+o)*2+0] / cnt;
        double var = g_stats[(b*4+o)*2+1] / cnt - mu*mu;
        smu[o] = (float)mu;
        siv[o] = rsqrtf(__fadd_rn((float)var, EPSF));
    }
    for (int i = o; i < 16*KNN; i += 128) sidx[i] = g_idx[(size_t)bn0*KNN + i];
    __syncthreads();
    float mu = smu[g], iv = siv[g];
    float gg = gn_g[o], gb = gn_b[o];
    const float* Ab = g_A + (size_t)b*NN*GD;
    for (int p = 0; p < 16; p++) {
        float c = g_C[(size_t)(bn0+p)*GD + o];
        float m = -FLT_MAX;
        #pragma unroll
        for (int k = 0; k < KNN; k++) {
            float v = Ab[(size_t)sidx[p*KNN+k]*GD + o] + c;
            v = __fadd_rn(__fmul_rn(__fmul_rn(__fsub_rn(v, mu), iv), gg), gb);
            v = (v >= 0.f) ? v : __fmul_rn(0.2f, v);
            m = fmaxf(m, v);
        }
        fsh[p][o] = m;
    }
    __syncthreads();
    float acc[16];
    float bp = b_proj[o];
    #pragma unroll
    for (int p = 0; p < 16; p++) acc[p] = bp;
    for (int c = 0; c < GD; c++) {
        float wv = g_wpT[c*128 + o];
        #pragma unroll
        for (int p = 0; p < 16; p++) acc[p] += fsh[p][c] * wv;
    }
    for (int p = 0; p < 16; p++) g_f2[(size_t)(bn0+p)*GD + o] = acc[p];
}

__global__ void k_grid(const float* __restrict__ pc)
{
    int b = blockIdx.x, t = threadIdx.x;
    __shared__ float r[4][256];
    __shared__ float sp[3];
    const float* p = pc + (size_t)b*NN*3;

    float mnx = FLT_MAX, mny = FLT_MAX, mxx = -FLT_MAX, mxy = -FLT_MAX;
    for (int i = t; i < NN; i += 256) {
        float x = p[i*3], y = p[i*3+1];
        mnx = fminf(mnx,x); mxx = fmaxf(mxx,x);
        mny = fminf(mny,y); mxy = fmaxf(mxy,y);
    }
    r[0][t]=mnx; r[1][t]=mxx; r[2][t]=mny; r[3][t]=mxy;
    __syncthreads();
    for (int s = 128; s; s >>= 1) {
        if (t < s) {
            r[0][t]=fminf(r[0][t],r[0][t+s]); r[1][t]=fmaxf(r[1][t],r[1][t+s]);
            r[2][t]=fminf(r[2][t],r[2][t+s]); r[3][t]=fmaxf(r[3][t],r[3][t+s]);
        }
        __syncthreads();
    }
    if (t == 0) {
        float ex = __fsub_rn(r[1][0], r[0][0]);
        float ey = __fsub_rn(r[3][0], r[2][0]);
        float gs = divfull(fmaxf(ex, ey), 197.0f);
        g_bp[b*8+0] = r[0][0];
        g_bp[b*8+1] = r[2][0];
        g_bp[b*8+2] = gs;
        sp[0] = r[0][0]; sp[1] = r[2][0]; sp[2] = gs;
    }
    __syncthreads();
    float pmx = sp[0], pmy = sp[1], gs = sp[2];

    mnx = FLT_MAX; mny = FLT_MAX; mxx = -FLT_MAX; mxy = -FLT_MAX;
    for (int i = t; i < NN; i += 256) {
        float ix = floorf(divfull(__fsub_rn(p[i*3],   pmx), gs));
        float iy = floorf(divfull(__fsub_rn(p[i*3+1], pmy), gs));
        mnx = fminf(mnx,ix); mxx = fmaxf(mxx,ix);
        mny = fminf(mny,iy); mxy = fmaxf(mxy,iy);
    }
    __syncthreads();
    r[0][t]=mnx; r[1][t]=mxx; r[2][t]=mny; r[3][t]=mxy;
    __syncthreads();
    for (int s = 128; s; s >>= 1) {
        if (t < s) {
            r[0][t]=fminf(r[0][t],r[0][t+s]); r[1][t]=fmaxf(r[1][t],r[1][t+s]);
            r[2][t]=fminf(r[2][t],r[2][t+s]); r[3][t]=fmaxf(r[3][t],r[3][t+s]);
        }
        __syncthreads();
    }
    if (t == 0) {
        float cx = floorf(__fmul_rn(__fadd_rn(__fadd_rn(r[1][0], 2.0f), r[0][0]), 0.5f));
        float cy = floorf(__fmul_rn(__fadd_rn(__fadd_rn(r[3][0], 2.0f), r[2][0]), 0.5f));
        g_bp[b*8+3] = (float)OBJ*0.5f - cx - 1.0f;
        g_bp[b*8+4] = (float)OBJ*0.5f - cy - 1.0f;
    }
}

__global__ void k_scatter(const float* __restrict__ pc)
{
    int bn = blockIdx.x, b = bn >> 11, o = threadIdx.x;
    float pmx = g_bp[b*8+0], pmy = g_bp[b*8+1], gs = g_bp[b*8+2];
    float shx = g_bp[b*8+3], shy = g_bp[b*8+4];
    float x = pc[(size_t)bn*3], y = pc[(size_t)bn*3+1];
    float ix = floorf(divfull(__fsub_rn(x, pmx), gs));
    float iy = floorf(divfull(__fsub_rn(y, pmy), gs));
    float val = g_f2[(size_t)bn*GD + o];
    float bx = ix + 1.0f + shx, by = iy + 1.0f + shy;
    #pragma unroll
    for (int ox = -1; ox <= 1; ox++)
    #pragma unroll
    for (int oy = -1; oy <= 1; oy++) {
        int lin = (int)(__fadd_rn(__fmul_rn(bx + (float)ox, 200.0f), by + (float)oy));
        if (lin >= 0 && lin < OBJ*OBJ) {
            int gx = lin / OBJ, gy = lin - gx*OBJ;
            atomicAdd(&g_res[(((size_t)b*GD + o)*IMGD + gx + 12)*IMGD + gy + 12], val);
        }
    }
}

// ---------------- FP16 tensor-core conv (m16n8k16), head fused into variant 1 ----------------
__global__ __launch_bounds__(128, 2) void k_conv_mma(int variant, float* __restrict__ outimg)
{
    const float*  in    = variant ? g_h1  : g_res;
    const __half* wt    = variant ? g_w2h : g_w1h;
    const float*  bias  = variant ? g_b2  : g_b1;
    const float*  resid = variant ? g_res : (const float*)0;
    float*        out   = g_h1;   // only variant 0 writes it

    __shared__ unsigned sA2[2][128][9];   // [buf][px][kpair]
    __shared__ unsigned sB2[2][128][9];   // [buf][oc][kpair]
    __shared__ float hb[3][128];          // fused-head accumulators (variant 1)
    __shared__ float swc[3*GD];

    int b = blockIdx.z;
    int pbase = blockIdx.x * 128;
    int t = threadIdx.x;             // 128
    int warp = t >> 5, lane = t & 31;
    int grp = lane >> 2, tid4 = lane & 3;
    int px0w = (warp & 1) * 64;
    int oc0w = (warp >> 1) * 64;

    int p_t = pbase + t;
    int row_t = p_t / IMGD;
    int col_t = p_t - row_t*IMGD;
    bool interior = (row_t >= 1) && (row_t <= IMGD-2) && (col_t >= 1) && (col_t <= IMGD-2);

    if (variant) {
        for (int i = t; i < 3*GD; i += 128) swc[i] = g_wc[i];
        hb[0][t] = 0.f; hb[1][t] = 0.f; hb[2][t] = 0.f;
    }

    float acc[4][8][4];
    #pragma unroll
    for (int mt = 0; mt < 4; mt++)
        #pragma unroll
        for (int nt = 0; nt < 8; nt++)
            #pragma unroll
            for (int r = 0; r < 4; r++) acc[mt][nt][r] = 0.f;

    const float* inb = in + (size_t)b*GD*HW;

    float raf[16];
    uint4 rb0, rb1;

    #pragma unroll
    for (int kk = 0; kk < 16; kk++) {
        int k = kk;
        int ci = k / 9;
        int r  = k - ci*9;
        int dh = r/3 - 1, dw = r - (r/3)*3 - 1;
        int ih = row_t + dh, iw = col_t + dw;
        float v = 0.f;
        if ((unsigned)ih < (unsigned)IMGD && (unsigned)iw < (unsigned)IMGD)
            v = inb[(size_t)ci*HW + ih*IMGD + iw];
        raf[kk] = v;
    }
    {
        const uint4* s = (const uint4*)(wt + (size_t)t*16);
        rb0 = s[0]; rb1 = s[1];
    }
    #pragma unroll
    for (int j = 0; j < 8; j++) sA2[0][t][j] = packh2(raf[2*j], raf[2*j+1]);
    sB2[0][t][0]=rb0.x; sB2[0][t][1]=rb0.y; sB2[0][t][2]=rb0.z; sB2[0][t][3]=rb0.w;
    sB2[0][t][4]=rb1.x; sB2[0][t][5]=rb1.y; sB2[0][t][6]=rb1.z; sB2[0][t][7]=rb1.w;
    __syncthreads();

    for (int i = 0; i < 72; i++) {
        int cur = i & 1;
        if (i < 71) {
            int kbase = (i + 1) * 16;
            const float* ibp = inb + row_t*IMGD + col_t;
            if (interior) {
                #pragma unroll
                for (int kk = 0; kk < 16; kk++) {
                    int k = kbase + kk;
                    int ci = k / 9;
                    int r  = k - ci*9;
                    int dh = r/3 - 1, dw = r - (r/3)*3 - 1;
                    raf[kk] = ibp[(size_t)ci*HW + dh*IMGD + dw];
                }
            } else {
                #pragma unroll
                for (int kk = 0; kk < 16; kk++) {
                    int k = kbase + kk;
                    int ci = k / 9;
                    int r  = k - ci*9;
                    int dh = r/3 - 1, dw = r - (r/3)*3 - 1;
                    int ih = row_t + dh, iw = col_t + dw;
                    float v = 0.f;
                    if ((unsigned)ih < (unsigned)IMGD && (unsigned)iw < (unsigned)IMGD)
                        v = inb[(size_t)ci*HW + ih*IMGD + iw];
                    raf[kk] = v;
                }
            }
            const uint4* s = (const uint4*)(wt + ((size_t)(i+1)*128 + t)*16);
            rb0 = s[0]; rb1 = s[1];
        }

        {
            unsigned bfr[8][2];
            #pragma unroll
            for (int nt = 0; nt < 8; nt++) {
                int col = oc0w + nt*8 + grp;
                bfr[nt][0] = sB2[cur][col][tid4];
                bfr[nt][1] = sB2[cur][col][tid4 + 4];
            }
            #pragma unroll
            for (int mt = 0; mt < 4; mt++) {
                int r0 = px0w + mt*16 + grp;
                unsigned a0 = sA2[cur][r0    ][tid4];
                unsigned a1 = sA2[cur][r0 + 8][tid4];
                unsigned a2 = sA2[cur][r0    ][tid4 + 4];
                unsigned a3 = sA2[cur][r0 + 8][tid4 + 4];
                #pragma unroll
                for (int nt = 0; nt < 8; nt++) {
                    asm volatile(
                        "mma.sync.aligned.m16n8k16.row.col.f32.f16.f16.f32 "
                        "{%0,%1,%2,%3}, {%4,%5,%6,%7}, {%8,%9}, {%0,%1,%2,%3};"
                        : "+f"(acc[mt][nt][0]), "+f"(acc[mt][nt][1]),
                          "+f"(acc[mt][nt][2]), "+f"(acc[mt][nt][3])
                        : "r"(a0), "r"(a1), "r"(a2), "r"(a3),
                          "r"(bfr[nt][0]), "r"(bfr[nt][1]));
                }
            }
        }

        if (i < 71) {
            int nxt = cur ^ 1;
            #pragma unroll
            for (int j = 0; j < 8; j++) sA2[nxt][t][j] = packh2(raf[2*j], raf[2*j+1]);
            sB2[nxt][t][0]=rb0.x; sB2[nxt][t][1]=rb0.y; sB2[nxt][t][2]=rb0.z; sB2[nxt][t][3]=rb0.w;
            sB2[nxt][t][4]=rb1.x; sB2[nxt][t][5]=rb1.y; sB2[nxt][t][6]=rb1.z; sB2[nxt][t][7]=rb1.w;
        }
        __syncthreads();
    }

    // epilogue
    if (!variant) {
        #pragma unroll
        for (int mt = 0; mt < 4; mt++) {
            int pxl = px0w + mt*16 + grp;
            #pragma unroll
            for (int nt = 0; nt < 8; nt++) {
                int oc = oc0w + nt*8 + tid4*2;
                float bv0 = bias[oc], bv1 = bias[oc+1];
                size_t base0 = ((size_t)b*GD + oc    )*HW + pbase;
                size_t base1 = ((size_t)b*GD + oc + 1)*HW + pbase;
                out[base0 + pxl    ] = fmaxf(acc[mt][nt][0] + bv0, 0.f);
                out[base1 + pxl    ] = fmaxf(acc[mt][nt][1] + bv1, 0.f);
                out[base0 + pxl + 8] = fmaxf(acc[mt][nt][2] + bv0, 0.f);
                out[base1 + pxl + 8] = fmaxf(acc[mt][nt][3] + bv1, 0.f);
            }
        }
    } else {
        // fused: h = relu(bn2(conv2) + res); hb[c][px] += wc[c][oc]*h
        #pragma unroll
        for (int mt = 0; mt < 4; mt++) {
            int pxl = px0w + mt*16 + grp;
            #pragma unroll
            for (int nt = 0; nt < 8; nt++) {
                int oc = oc0w + nt*8 + tid4*2;
                float bv0 = bias[oc], bv1 = bias[oc+1];
                size_t base0 = ((size_t)b*GD + oc    )*HW + pbase;
                size_t base1 = ((size_t)b*GD + oc + 1)*HW + pbase;
                float v00 = fmaxf(__fadd_rn(acc[mt][nt][0] + bv0, resid[base0 + pxl]), 0.f);
                float v01 = fmaxf(__fadd_rn(acc[mt][nt][1] + bv1, resid[base1 + pxl]), 0.f);
                float v10 = fmaxf(__fadd_rn(acc[mt][nt][2] + bv0, resid[base0 + pxl + 8]), 0.f);
                float v11 = fmaxf(__fadd_rn(acc[mt][nt][3] + bv1, resid[base1 + pxl + 8]), 0.f);
                #pragma unroll
                for (int c = 0; c < 3; c++) {
                    float w0 = swc[c*GD + oc], w1 = swc[c*GD + oc + 1];
                    atomicAdd(&hb[c][pxl    ], w0*v00 + w1*v01);
                    atomicAdd(&hb[c][pxl + 8], w0*v10 + w1*v11);
                }
            }
        }
        __syncthreads();
        {
            float s0 = hb[0][t] + g_bc[0];
            float s1 = hb[1][t] + g_bc[1];
            float s2 = hb[2][t] + g_bc[2];
            float i0 = __fdiv_rn(1.f, __fadd_rn(1.f, expf(-s0)));
            float i1 = __fdiv_rn(1.f, __fadd_rn(1.f, expf(-s1)));
            float i2 = __fdiv_rn(1.f, __fadd_rn(1.f, expf(-s2)));
            outimg[((size_t)b*3 + 0)*HW + p_t] = __fdiv_rn(__fsub_rn(i0, 0.485f), 0.229f);
            outimg[((size_t)b*3 + 1)*HW + p_t] = __fdiv_rn(__fsub_rn(i1, 0.456f), 0.224f);
            outimg[((size_t)b*3 + 2)*HW + p_t] = __fdiv_rn(__fsub_rn(i2, 0.406f), 0.225f);
        }
    }
}

extern "C" void kernel_launch(void* const* d_in, const int* in_sizes, int n_in,
                              void* d_out, int out_size)
{
    const float* opc    = (const float*)d_in[0];
    const float* pc     = (const float*)d_in[1];
    const float* W_in   = (const float*)d_in[2];
    const float* b_in   = (const float*)d_in[3];
    const float* Wg     = (const float*)d_in[4];
    const float* gn_g   = (const float*)d_in[5];
    const float* gn_b   = (const float*)d_in[6];
    const float* Wp     = (const float*)d_in[7];
    const float* b_proj = (const float*)d_in[8];
    const float* W1     = (const float*)d_in[9];
    const float* bn1g   = (const float*)d_in[10];
    const float* bn1b   = (const float*)d_in[11];
    const float* bn1m   = (const float*)d_in[12];
    const float* bn1v   = (const float*)d_in[13];
    const float* W2     = (const float*)d_in[14];
    const float* bn2g   = (const float*)d_in[15];
    const float* bn2b   = (const float*)d_in[16];
    const float* bn2m   = (const float*)d_in[17];
    const float* bn2v   = (const float*)d_in[18];
    const float* Wimgc  = (const float*)d_in[19];
    const float* bimgc  = (const float*)d_in[20];
    const float* Wimg   = (const float*)d_in[21];
    const float* bimg   = (const float*)d_in[22];
    float* out = (float*)d_out;

    k_init<<<4096, 256>>>(W1, bn1g, bn1b, bn1m, bn1v,
                          W2, bn2g, bn2b, bn2m, bn2v,
                          Wg, Wp, Wimgc, bimgc, Wimg, bimg);

    k_x<<<BB*NN, 64>>>(opc, W_in, b_in);
    k_knn<<<BB*NN/4, 128>>>(opc);
    k_projAC<<<BB*NN, 128>>>();
    k_stats<<<BB*NN, 128>>>();
    k_f2<<<BB*NN/16, 128>>>(gn_g, gn_b, b_proj);

    k_grid<<<BB, 256>>>(pc);
    k_scatter<<<BB*NN, 128>>>(pc);

    dim3 cgrid(HW/128, 1, BB);
    k_conv_mma<<<cgrid, 128>>>(0, out);
    k_conv_mma<<<cgrid, 128>>>(1, out);
}

// round 15
// speedup vs baseline: 1.2718x; 1.2718x over previous
#include <cuda_runtime.h>
#include <cuda_fp16.h>
#include <math.h>
#include <float.h>
#include <stdint.h>

#define BB 4
#define NN 2048
#define KNN 20
#define TD 64
#define GD 128
#define OBJ 200
#define IMGD 224
#define HW (IMGD*IMGD)
#define EPSF 1e-5f

// XLA:GPU f32 division (fdiv -> div.full.f32) — correctness-critical for grid placement
__device__ __forceinline__ float divfull(float a, float b)
{
    float r;
    asm("div.full.f32 %0, %1, %2;" : "=f"(r) : "f"(a), "f"(b));
    return r;
}

__device__ __forceinline__ unsigned packh2(float a, float b)
{
    __half2 h = __floats2half2_rn(a, b);
    return *reinterpret_cast<unsigned*>(&h);
}

__device__ float  g_x[BB*NN*TD];
__device__ int    g_idx[BB*NN*KNN];
__device__ float  g_A[BB*NN*GD];
__device__ float  g_C[BB*NN*GD];
__device__ double g_stats[BB*4*2];
__device__ float  g_f2[BB*NN*GD];
__device__ float  g_bp[BB*8];
__device__ float  g_res[BB*GD*HW];
__device__ float  g_h1 [BB*GD*HW];
__device__ float  g_h2 [BB*GD*HW];
__device__ __half g_w1h[1152*GD];     // chunked [c][oc][16k] fp16, BN folded
__device__ __half g_w2h[1152*GD];
__device__ float  g_b1[GD];
__device__ float  g_b2[GD];
__device__ float  g_wgT[128*GD];
__device__ float  g_wpT[GD*GD];
__device__ float  g_wc[3*GD];
__device__ float  g_bc[3];

// ---------------- merged zero + weight prep ----------------
__global__ void k_init(const float* __restrict__ W1, const float* __restrict__ bn1g,
                       const float* __restrict__ bn1b, const float* __restrict__ bn1m,
                       const float* __restrict__ bn1v,
                       const float* __restrict__ W2, const float* __restrict__ bn2g,
                       const float* __restrict__ bn2b, const float* __restrict__ bn2m,
                       const float* __restrict__ bn2v,
                       const float* __restrict__ Wg, const float* __restrict__ Wp,
                       const float* __restrict__ Wimgc, const float* __restrict__ bimgc,
                       const float* __restrict__ Wimg, const float* __restrict__ bimg)
{
    int bid = blockIdx.x, t = threadIdx.x;
    size_t i = (size_t)bid*blockDim.x + t;

    size_t n4 = ((size_t)BB*GD*HW)/4;
    float4* r4 = (float4*)g_res;
    float4 z = make_float4(0.f,0.f,0.f,0.f);
    for (size_t j = i; j < n4; j += (size_t)gridDim.x*blockDim.x) r4[j] = z;
    if (i < BB*4*2) ((double*)g_stats)[i] = 0.0;

    if (bid < 1152) {
        int variant = (bid >= 576);
        int e = (variant ? bid - 576 : bid)*256 + t;
        const float* W  = variant ? W2   : W1;
        const float* ga = variant ? bn2g : bn1g;
        const float* be = variant ? bn2b : bn1b;
        const float* mm = variant ? bn2m : bn1m;
        const float* vv = variant ? bn2v : bn1v;
        __half* wh  = variant ? g_w2h : g_w1h;
        float* bias = variant ? g_b2  : g_b1;
        if (e < 128) {
            float sc = ga[e] * rsqrtf(__fadd_rn(vv[e], EPSF));
            bias[e] = __fsub_rn(be[e], __fmul_rn(mm[e], sc));
        }
        if (e < 1152*128) {
            int oc = e / 1152;
            int k  = e - oc*1152;
            float sc = ga[oc] * rsqrtf(__fadd_rn(vv[oc], EPSF));
            int c  = k >> 4, kk = k & 15;
            wh[((size_t)c*128 + oc)*16 + kk] = __float2half_rn(__fmul_rn(W[e], sc));
        }
    } else if (bid < 1216) {
        int e = (bid - 1152)*256 + t;
        int o = e >> 7, c = e & 127;
        g_wgT[c*128 + o] = Wg[e];
        g_wpT[c*128 + o] = Wp[e];
    } else if (bid == 1216) {
        for (int idx = t; idx < 384; idx += 256) {
            int j = idx / 128, c = idx - j*128;
            float s = 0.f;
            for (int o = 0; o < 128; o++) s += Wimg[j*128+o] * Wimgc[o*128+c];
            g_wc[idx] = s;
        }
        if (t < 3) {
            float s = bimg[t];
            for (int o = 0; o < 128; o++) s += Wimg[t*128+o] * bimgc[o];
            g_bc[t] = s;
        }
    }
}

__global__ void k_x(const float* __restrict__ opc, const float* __restrict__ W_in,
                    const float* __restrict__ b_in)
{
    int bn = blockIdx.x, c = threadIdx.x;   // 64
    __shared__ float p[3];
    if (c < 3) p[c] = opc[(size_t)bn*3 + c];
    __syncthreads();
    float v = __fadd_rn(__fadd_rn(__fadd_rn(__fmul_rn(p[0], W_in[c*3+0]),
                        __fmul_rn(p[1], W_in[c*3+1])), __fmul_rn(p[2], W_in[c*3+2])), b_in[c]);
    g_x[(size_t)bn*TD + c] = v;
}

__global__ __launch_bounds__(128) void k_knn(const float* __restrict__ opc)
{
    __shared__ float sbuf[4*NN];
    float* sx  = sbuf;
    float* sy  = sbuf + NN;
    float* sz  = sbuf + 2*NN;
    float* ssq = sbuf + 3*NN;

    int b  = blockIdx.x >> 9;
    int nb = (blockIdx.x & 511) * 4;
    int t = threadIdx.x, w = t >> 5, lane = t & 31;
    const float* pcb = opc + (size_t)b*NN*3;
    for (int i = t; i < NN; i += 128) {
        float x = pcb[i*3+0], y = pcb[i*3+1], zz = pcb[i*3+2];
        sx[i] = x; sy[i] = y; sz[i] = zz;
        float s01 = __fadd_rn(__fmul_rn(x,x), __fmul_rn(y,y));
        ssq[i] = __fadd_rn(s01, __fmul_rn(zz,zz));
    }
    __syncthreads();

    int n = nb + w;
    float qx = sx[n], qy = sy[n], qz = sz[n], qsq = ssq[n];

    float d[KNN]; int id[KNN];
    #pragma unroll
    for (int j = 0; j < KNN; j++){ d[j] = FLT_MAX; id[j] = 0x7fffffff; }
    float worst = FLT_MAX; int wpos = 0;

    for (int m = lane; m < NN; m += 32) {
        float dot  = __fadd_rn(__fadd_rn(__fmul_rn(qx, sx[m]), __fmul_rn(qy, sy[m])),
                               __fmul_rn(qz, sz[m]));
        float dist = __fsub_rn(__fadd_rn(qsq, ssq[m]), __fmul_rn(2.0f, dot));
        if (dist < worst) {
            #pragma unroll
            for (int j = 0; j < KNN; j++) if (j == wpos){ d[j] = dist; id[j] = m; }
            worst = -FLT_MAX;
            #pragma unroll
            for (int j = 0; j < KNN; j++) if (d[j] > worst){ worst = d[j]; wpos = j; }
        }
    }
    __syncthreads();

    float* cd  = sbuf;
    int*   cid = (int*)(sbuf + 2560);
    int base = w*640 + lane*KNN;
    #pragma unroll
    for (int j = 0; j < KNN; j++){ cd[base+j] = d[j]; cid[base+j] = id[j]; }
    __syncwarp();

    int* out = g_idx + ((size_t)(b*NN + n))*KNN;
    for (int r = 0; r < KNN; r++) {
        float mv = FLT_MAX; int mp = 0; int midx = 0x7fffffff;
        #pragma unroll
        for (int j = 0; j < KNN; j++) {
            float v = cd[w*640 + lane*KNN + j];
            int   ii = cid[w*640 + lane*KNN + j];
            if (v < mv || (v == mv && ii < midx)) { mv = v; midx = ii; mp = lane*KNN + j; }
        }
        for (int off = 16; off; off >>= 1) {
            float ov = __shfl_down_sync(0xffffffffu, mv, off);
            int   oi = __shfl_down_sync(0xffffffffu, midx, off);
            int   op = __shfl_down_sync(0xffffffffu, mp, off);
            if (ov < mv || (ov == mv && oi < midx)) { mv = ov; midx = oi; mp = op; }
        }
        mp = __shfl_sync(0xffffffffu, mp, 0);
        if (lane == 0) { out[r] = cid[w*640 + mp]; cd[w*640 + mp] = FLT_MAX; }
        __syncwarp();
    }
}

__global__ void k_projAC()
{
    int bn = blockIdx.x, o = threadIdx.x;  // 128
    __shared__ float xs[TD];
    if (o < TD) xs[o] = g_x[(size_t)bn*TD + o];
    __syncthreads();
    float a = 0.f, c2 = 0.f;
    #pragma unroll 8
    for (int c = 0; c < TD; c++) {
        float xv = xs[c];
        a  += xv * g_wgT[c*128 + o];
        c2 += xv * g_wgT[(c+TD)*128 + o];
    }
    g_A[(size_t)bn*GD + o] = a;
    g_C[(size_t)bn*GD + o] = c2 - a;
}

__global__ void k_stats()
{
    int bn = blockIdx.x, b = bn >> 11, o = threadIdx.x;
    __shared__ int sidx[KNN];
    if (o < KNN) sidx[o] = g_idx[(size_t)bn*KNN + o];
    __syncthreads();
    float c = g_C[(size_t)bn*GD + o];
    const float* Ab = g_A + (size_t)b*NN*GD;
    float s1 = 0.f, s2 = 0.f;
    #pragma unroll
    for (int k = 0; k < KNN; k++) {
        float v = Ab[(size_t)sidx[k]*GD + o] + c;
        s1 += v; s2 += v*v;
    }
    for (int off = 16; off; off >>= 1) {
        s1 += __shfl_down_sync(0xffffffffu, s1, off);
        s2 += __shfl_down_sync(0xffffffffu, s2, off);
    }
    if ((o & 31) == 0) {
        int g = o >> 5;
        atomicAdd(&g_stats[(b*4+g)*2+0], (double)s1);
        atomicAdd(&g_stats[(b*4+g)*2+1], (double)s2);
    }
}

// finstats folded: each block recomputes mu/iv from g_stats (bit-identical math)
__global__ void k_f2(const float* __restrict__ gn_g, const float* __restrict__ gn_b,
                     const float* __restrict__ b_proj)
{
    __shared__ float fsh[16][GD];
    __shared__ int   sidx[16*KNN];
    __shared__ float smu[4], siv[4];
    int bn0 = blockIdx.x * 16;
    int b   = bn0 >> 11;
    int o   = threadIdx.x;
    int g   = o >> 5;
    if (o < 4) {
        double cnt = (double)NN * KNN * 32.0;
        double mu = g_stats[(b*4+o)*2+0] / cnt;
        double var = g_stats[(b*4+o)*2+1] / cnt - mu*mu;
        smu[o] = (float)mu;
        siv[o] = rsqrtf(__fadd_rn((float)var, EPSF));
    }
    for (int i = o; i < 16*KNN; i += 128) sidx[i] = g_idx[(size_t)bn0*KNN + i];
    __syncthreads();
    float mu = smu[g], iv = siv[g];
    float gg = gn_g[o], gb = gn_b[o];
    const float* Ab = g_A + (size_t)b*NN*GD;
    for (int p = 0; p < 16; p++) {
        float c = g_C[(size_t)(bn0+p)*GD + o];
        float m = -FLT_MAX;
        #pragma unroll
        for (int k = 0; k < KNN; k++) {
            float v = Ab[(size_t)sidx[p*KNN+k]*GD + o] + c;
            v = __fadd_rn(__fmul_rn(__fmul_rn(__fsub_rn(v, mu), iv), gg), gb);
            v = (v >= 0.f) ? v : __fmul_rn(0.2f, v);
            m = fmaxf(m, v);
        }
        fsh[p][o] = m;
    }
    __syncthreads();
    float acc[16];
    float bp = b_proj[o];
    #pragma unroll
    for (int p = 0; p < 16; p++) acc[p] = bp;
    for (int c = 0; c < GD; c++) {
        float wv = g_wpT[c*128 + o];
        #pragma unroll
        for (int p = 0; p < 16; p++) acc[p] += fsh[p][c] * wv;
    }
    for (int p = 0; p < 16; p++) g_f2[(size_t)(bn0+p)*GD + o] = acc[p];
}

__global__ void k_grid(const float* __restrict__ pc)
{
    int b = blockIdx.x, t = threadIdx.x;
    __shared__ float r[4][256];
    __shared__ float sp[3];
    const float* p = pc + (size_t)b*NN*3;

    float mnx = FLT_MAX, mny = FLT_MAX, mxx = -FLT_MAX, mxy = -FLT_MAX;
    for (int i = t; i < NN; i += 256) {
        float x = p[i*3], y = p[i*3+1];
        mnx = fminf(mnx,x); mxx = fmaxf(mxx,x);
        mny = fminf(mny,y); mxy = fmaxf(mxy,y);
    }
    r[0][t]=mnx; r[1][t]=mxx; r[2][t]=mny; r[3][t]=mxy;
    __syncthreads();
    for (int s = 128; s; s >>= 1) {
        if (t < s) {
            r[0][t]=fminf(r[0][t],r[0][t+s]); r[1][t]=fmaxf(r[1][t],r[1][t+s]);
            r[2][t]=fminf(r[2][t],r[2][t+s]); r[3][t]=fmaxf(r[3][t],r[3][t+s]);
        }
        __syncthreads();
    }
    if (t == 0) {
        float ex = __fsub_rn(r[1][0], r[0][0]);
        float ey = __fsub_rn(r[3][0], r[2][0]);
        float gs = divfull(fmaxf(ex, ey), 197.0f);
        g_bp[b*8+0] = r[0][0];
        g_bp[b*8+1] = r[2][0];
        g_bp[b*8+2] = gs;
        sp[0] = r[0][0]; sp[1] = r[2][0]; sp[2] = gs;
    }
    __syncthreads();
    float pmx = sp[0], pmy = sp[1], gs = sp[2];

    mnx = FLT_MAX; mny = FLT_MAX; mxx = -FLT_MAX; mxy = -FLT_MAX;
    for (int i = t; i < NN; i += 256) {
        float ix = floorf(divfull(__fsub_rn(p[i*3],   pmx), gs));
        float iy = floorf(divfull(__fsub_rn(p[i*3+1], pmy), gs));
        mnx = fminf(mnx,ix); mxx = fmaxf(mxx,ix);
        mny = fminf(mny,iy); mxy = fmaxf(mxy,iy);
    }
    __syncthreads();
    r[0][t]=mnx; r[1][t]=mxx; r[2][t]=mny; r[3][t]=mxy;
    __syncthreads();
    for (int s = 128; s; s >>= 1) {
        if (t < s) {
            r[0][t]=fminf(r[0][t],r[0][t+s]); r[1][t]=fmaxf(r[1][t],r[1][t+s]);
            r[2][t]=fminf(r[2][t],r[2][t+s]); r[3][t]=fmaxf(r[3][t],r[3][t+s]);
        }
        __syncthreads();
    }
    if (t == 0) {
        float cx = floorf(__fmul_rn(__fadd_rn(__fadd_rn(r[1][0], 2.0f), r[0][0]), 0.5f));
        float cy = floorf(__fmul_rn(__fadd_rn(__fadd_rn(r[3][0], 2.0f), r[2][0]), 0.5f));
        g_bp[b*8+3] = (float)OBJ*0.5f - cx - 1.0f;
        g_bp[b*8+4] = (float)OBJ*0.5f - cy - 1.0f;
    }
}

__global__ void k_scatter(const float* __restrict__ pc)
{
    int bn = blockIdx.x, b = bn >> 11, o = threadIdx.x;
    float pmx = g_bp[b*8+0], pmy = g_bp[b*8+1], gs = g_bp[b*8+2];
    float shx = g_bp[b*8+3], shy = g_bp[b*8+4];
    float x = pc[(size_t)bn*3], y = pc[(size_t)bn*3+1];
    float ix = floorf(divfull(__fsub_rn(x, pmx), gs));
    float iy = floorf(divfull(__fsub_rn(y, pmy), gs));
    float val = g_f2[(size_t)bn*GD + o];
    float bx = ix + 1.0f + shx, by = iy + 1.0f + shy;
    #pragma unroll
    for (int ox = -1; ox <= 1; ox++)
    #pragma unroll
    for (int oy = -1; oy <= 1; oy++) {
        int lin = (int)(__fadd_rn(__fmul_rn(bx + (float)ox, 200.0f), by + (float)oy));
        if (lin >= 0 && lin < OBJ*OBJ) {
            int gx = lin / OBJ, gy = lin - gx*OBJ;
            atomicAdd(&g_res[(((size_t)b*GD + o)*IMGD + gx + 12)*IMGD + gy + 12], val);
        }
    }
}

// ---------------- FP16 tensor-core conv (m16n8k16), 256 thr / 8 warps / warp tile 32x64 ----------------
__global__ __launch_bounds__(256, 2) void k_conv_mma(int variant)
{
    const float*  in    = variant ? g_h1  : g_res;
    const __half* wt    = variant ? g_w2h : g_w1h;
    const float*  bias  = variant ? g_b2  : g_b1;
    const float*  resid = variant ? g_res : (const float*)0;
    float*        out   = variant ? g_h2  : g_h1;

    __shared__ unsigned sA2[2][128][9];   // [buf][px][kpair]
    __shared__ unsigned sB2[2][128][9];   // [buf][oc][kpair]

    int b = blockIdx.z;
    int pbase = blockIdx.x * 128;
    int t = threadIdx.x;             // 256
    int warp = t >> 5, lane = t & 31;
    int grp = lane >> 2, tid4 = lane & 3;
    int px0w = (warp & 3) * 32;
    int oc0w = (warp >> 2) * 64;

    int px = t & 127;                // fill: pixel
    int kh = t >> 7;                 // fill: k-half (0/1)
    int p_t = pbase + px;
    int row_t = p_t / IMGD;
    int col_t = p_t - row_t*IMGD;

    float acc[2][8][4];
    #pragma unroll
    for (int mt = 0; mt < 2; mt++)
        #pragma unroll
        for (int nt = 0; nt < 8; nt++)
            #pragma unroll
            for (int r = 0; r < 4; r++) acc[mt][nt][r] = 0.f;

    const float* inb = in + (size_t)b*GD*HW;

    float raf[8];
    uint4 rbv;

    // prologue: chunk 0 (this thread's 8 k-values: kh*8 .. kh*8+7)
    #pragma unroll
    for (int j = 0; j < 8; j++) {
        int k = kh*8 + j;
        int ci = k / 9;
        int r  = k - ci*9;
        int dh = r/3 - 1, dw = r - (r/3)*3 - 1;
        int ih = row_t + dh, iw = col_t + dw;
        float v = 0.f;
        if ((unsigned)ih < (unsigned)IMGD && (unsigned)iw < (unsigned)IMGD)
            v = inb[(size_t)ci*HW + ih*IMGD + iw];
        raf[j] = v;
    }
    rbv = ((const uint4*)(wt + (size_t)px*16))[kh];
    #pragma unroll
    for (int j = 0; j < 4; j++) sA2[0][px][kh*4 + j] = packh2(raf[2*j], raf[2*j+1]);
    sB2[0][px][kh*4+0]=rbv.x; sB2[0][px][kh*4+1]=rbv.y;
    sB2[0][px][kh*4+2]=rbv.z; sB2[0][px][kh*4+3]=rbv.w;
    __syncthreads();

    for (int i = 0; i < 72; i++) {
        int cur = i & 1;
        if (i < 71) {
            int kbase = (i + 1) * 16;
            #pragma unroll
            for (int j = 0; j < 8; j++) {
                int k = kbase + kh*8 + j;
                int ci = k / 9;
                int r  = k - ci*9;
                int dh = r/3 - 1, dw = r - (r/3)*3 - 1;
                int ih = row_t + dh, iw = col_t + dw;
                float v = 0.f;
                if ((unsigned)ih < (unsigned)IMGD && (unsigned)iw < (unsigned)IMGD)
                    v = inb[(size_t)ci*HW + ih*IMGD + iw];
                raf[j] = v;
            }
            rbv = ((const uint4*)(wt + ((size_t)(i+1)*128 + px)*16))[kh];
        }

        {
            unsigned bfr[8][2];
            #pragma unroll
            for (int nt = 0; nt < 8; nt++) {
                int col = oc0w + nt*8 + grp;
                bfr[nt][0] = sB2[cur][col][tid4];
                bfr[nt][1] = sB2[cur][col][tid4 + 4];
            }
            #pragma unroll
            for (int mt = 0; mt < 2; mt++) {
                int r0 = px0w + mt*16 + grp;
                unsigned a0 = sA2[cur][r0    ][tid4];
                unsigned a1 = sA2[cur][r0 + 8][tid4];
                unsigned a2 = sA2[cur][r0    ][tid4 + 4];
                unsigned a3 = sA2[cur][r0 + 8][tid4 + 4];
                #pragma unroll
                for (int nt = 0; nt < 8; nt++) {
                    asm volatile(
                        "mma.sync.aligned.m16n8k16.row.col.f32.f16.f16.f32 "
                        "{%0,%1,%2,%3}, {%4,%5,%6,%7}, {%8,%9}, {%0,%1,%2,%3};"
                        : "+f"(acc[mt][nt][0]), "+f"(acc[mt][nt][1]),
                          "+f"(acc[mt][nt][2]), "+f"(acc[mt][nt][3])
                        : "r"(a0), "r"(a1), "r"(a2), "r"(a3),
                          "r"(bfr[nt][0]), "r"(bfr[nt][1]));
                }
            }
        }

        if (i < 71) {
            int nxt = cur ^ 1;
            #pragma unroll
            for (int j = 0; j < 4; j++) sA2[nxt][px][kh*4 + j] = packh2(raf[2*j], raf[2*j+1]);
            sB2[nxt][px][kh*4+0]=rbv.x; sB2[nxt][px][kh*4+1]=rbv.y;
            sB2[nxt][px][kh*4+2]=rbv.z; sB2[nxt][px][kh*4+3]=rbv.w;
        }
        __syncthreads();
    }

    // epilogue: bias (+resid) + relu
    #pragma unroll
    for (int mt = 0; mt < 2; mt++) {
        int pxl = px0w + mt*16 + grp;
        #pragma unroll
        for (int nt = 0; nt < 8; nt++) {
            int oc = oc0w + nt*8 + tid4*2;
            float bv0 = bias[oc], bv1 = bias[oc+1];
            size_t base0 = ((size_t)b*GD + oc    )*HW + pbase;
            size_t base1 = ((size_t)b*GD + oc + 1)*HW + pbase;
            float v00 = acc[mt][nt][0] + bv0;
            float v01 = acc[mt][nt][1] + bv1;
            float v10 = acc[mt][nt][2] + bv0;
            float v11 = acc[mt][nt][3] + bv1;
            if (resid) {
                v00 += resid[base0 + pxl];
                v01 += resid[base1 + pxl];
                v10 += resid[base0 + pxl + 8];
                v11 += resid[base1 + pxl + 8];
            }
            out[base0 + pxl    ] = fmaxf(v00, 0.f);
            out[base1 + pxl    ] = fmaxf(v01, 0.f);
            out[base0 + pxl + 8] = fmaxf(v10, 0.f);
            out[base1 + pxl + 8] = fmaxf(v11, 0.f);
        }
    }
}

__global__ void k_final(float* __restrict__ out)
{
    __shared__ float wc[3*GD];
    __shared__ float bc[3];
    int t = threadIdx.x;             // 128
    for (int i = t; i < 3*GD; i += 128) wc[i] = g_wc[i];
    if (t < 3) bc[t] = g_bc[t];
    __syncthreads();
    int b = blockIdx.z;
    int p = blockIdx.x * 128 + t;
    const float* h = g_h2 + (size_t)b*GD*HW + p;
    float s0 = bc[0], s1 = bc[1], s2 = bc[2];
    #pragma unroll 4
    for (int c = 0; c < GD; c++) {
        float v = h[(size_t)c*HW];
        s0 += v * wc[c];
        s1 += v * wc[GD + c];
        s2 += v * wc[2*GD + c];
    }
    float i0 = __fdiv_rn(1.f, __fadd_rn(1.f, expf(-s0)));
    float i1 = __fdiv_rn(1.f, __fadd_rn(1.f, expf(-s1)));
    float i2 = __fdiv_rn(1.f, __fadd_rn(1.f, expf(-s2)));
    out[((size_t)b*3 + 0)*HW + p] = __fdiv_rn(__fsub_rn(i0, 0.485f), 0.229f);
    out[((size_t)b*3 + 1)*HW + p] = __fdiv_rn(__fsub_rn(i1, 0.456f), 0.224f);
    out[((size_t)b*3 + 2)*HW + p] = __fdiv_rn(__fsub_rn(i2, 0.406f), 0.225f);
}

extern "C" void kernel_launch(void* const* d_in, const int* in_sizes, int n_in,
                              void* d_out, int out_size)
{
    const float* opc    = (const float*)d_in[0];
    const float* pc     = (const float*)d_in[1];
    const float* W_in   = (const float*)d_in[2];
    const float* b_in   = (const float*)d_in[3];
    const float* Wg     = (const float*)d_in[4];
    const float* gn_g   = (const float*)d_in[5];
    const float* gn_b   = (const float*)d_in[6];
    const float* Wp     = (const float*)d_in[7];
    const float* b_proj = (const float*)d_in[8];
    const float* W1     = (const float*)d_in[9];
    const float* bn1g   = (const float*)d_in[10];
    const float* bn1b   = (const float*)d_in[11];
    const float* bn1m   = (const float*)d_in[12];
    const float* bn1v   = (const float*)d_in[13];
    const float* W2     = (const float*)d_in[14];
    const float* bn2g   = (const float*)d_in[15];
    const float* bn2b   = (const float*)d_in[16];
    const float* bn2m   = (const float*)d_in[17];
    const float* bn2v   = (const float*)d_in[18];
    const float* Wimgc  = (const float*)d_in[19];
    const float* bimgc  = (const float*)d_in[20];
    const float* Wimg   = (const float*)d_in[21];
    const float* bimg   = (const float*)d_in[22];
    float* out = (float*)d_out;

    k_init<<<4096, 256>>>(W1, bn1g, bn1b, bn1m, bn1v,
                          W2, bn2g, bn2b, bn2m, bn2v,
                          Wg, Wp, Wimgc, bimgc, Wimg, bimg);

    k_x<<<BB*NN, 64>>>(opc, W_in, b_in);
    k_knn<<<BB*NN/4, 128>>>(opc);
    k_projAC<<<BB*NN, 128>>>();
    k_stats<<<BB*NN, 128>>>();
    k_f2<<<BB*NN/16, 128>>>(gn_g, gn_b, b_proj);

    k_grid<<<BB, 256>>>(pc);
    k_scatter<<<BB*NN, 128>>>(pc);

    dim3 cgrid(HW/128, 1, BB);
    k_conv_mma<<<cgrid, 256>>>(0);
    k_conv_mma<<<cgrid, 256>>>(1);

    dim3 fgrid(HW/128, 1, BB);
    k_final<<<fgrid, 128>>>(out);
}

// round 16
// speedup vs baseline: 1.2763x; 1.0035x over previous
#include <cuda_runtime.h>
#include <cuda_fp16.h>
#include <math.h>
#include <float.h>
#include <stdint.h>

#define BB 4
#define NN 2048
#define KNN 20
#define TD 64
#define GD 128
#define OBJ 200
#define IMGD 224
#define HW (IMGD*IMGD)
#define EPSF 1e-5f

// XLA:GPU f32 division (fdiv -> div.full.f32) — correctness-critical for grid placement
__device__ __forceinline__ float divfull(float a, float b)
{
    float r;
    asm("div.full.f32 %0, %1, %2;" : "=f"(r) : "f"(a), "f"(b));
    return r;
}

__device__ float  g_x_unused;   // placeholder (k_x merged into k_xAC)
__device__ int    g_idx[BB*NN*KNN];
__device__ float  g_A[BB*NN*GD];
__device__ float  g_C[BB*NN*GD];
__device__ double g_stats[BB*4*2];
__device__ float  g_f2[BB*NN*GD];
__device__ float  g_bp[BB*8];
__device__ float  g_res[BB*GD*HW];     // fp32 (scatter target + residual)
__device__ __half g_resh[BB*GD*HW];    // fp16 copy for conv1 input
__device__ __half g_h1h[BB*GD*HW];     // conv1 output (fp16)
__device__ __half g_w1h[1152*GD];      // chunked [c][oc][16k] fp16, BN folded
__device__ __half g_w2h[1152*GD];
__device__ float  g_b1[GD];
__device__ float  g_b2[GD];
__device__ float  g_wgT[128*GD];
__device__ float  g_wpT[GD*GD];
__device__ float  g_wc[3*GD];
__device__ float  g_bc[3];

// ---------------- merged zero + weight prep ----------------
__global__ void k_init(const float* __restrict__ W1, const float* __restrict__ bn1g,
                       const float* __restrict__ bn1b, const float* __restrict__ bn1m,
                       const float* __restrict__ bn1v,
                       const float* __restrict__ W2, const float* __restrict__ bn2g,
                       const float* __restrict__ bn2b, const float* __restrict__ bn2m,
                       const float* __restrict__ bn2v,
                       const float* __restrict__ Wg, const float* __restrict__ Wp,
                       const float* __restrict__ Wimgc, const float* __restrict__ bimgc,
                       const float* __restrict__ Wimg, const float* __restrict__ bimg)
{
    int bid = blockIdx.x, t = threadIdx.x;
    size_t i = (size_t)bid*blockDim.x + t;

    size_t n4 = ((size_t)BB*GD*HW)/4;
    float4* r4 = (float4*)g_res;
    float4 z = make_float4(0.f,0.f,0.f,0.f);
    for (size_t j = i; j < n4; j += (size_t)gridDim.x*blockDim.x) r4[j] = z;
    if (i < BB*4*2) ((double*)g_stats)[i] = 0.0;

    if (bid < 1152) {
        int variant = (bid >= 576);
        int e = (variant ? bid - 576 : bid)*256 + t;
        const float* W  = variant ? W2   : W1;
        const float* ga = variant ? bn2g : bn1g;
        const float* be = variant ? bn2b : bn1b;
        const float* mm = variant ? bn2m : bn1m;
        const float* vv = variant ? bn2v : bn1v;
        __half* wh  = variant ? g_w2h : g_w1h;
        float* bias = variant ? g_b2  : g_b1;
        if (e < 128) {
            float sc = ga[e] * rsqrtf(__fadd_rn(vv[e], EPSF));
            bias[e] = __fsub_rn(be[e], __fmul_rn(mm[e], sc));
        }
        if (e < 1152*128) {
            int oc = e / 1152;
            int k  = e - oc*1152;
            float sc = ga[oc] * rsqrtf(__fadd_rn(vv[oc], EPSF));
            int c  = k >> 4, kk = k & 15;
            wh[((size_t)c*128 + oc)*16 + kk] = __float2half_rn(__fmul_rn(W[e], sc));
        }
    } else if (bid < 1216) {
        int e = (bid - 1152)*256 + t;
        int o = e >> 7, c = e & 127;
        g_wgT[c*128 + o] = Wg[e];
        g_wpT[c*128 + o] = Wp[e];
    } else if (bid == 1216) {
        for (int idx = t; idx < 384; idx += 256) {
            int j = idx / 128, c = idx - j*128;
            float s = 0.f;
            for (int o = 0; o < 128; o++) s += Wimg[j*128+o] * Wimgc[o*128+c];
            g_wc[idx] = s;
        }
        if (t < 3) {
            float s = bimg[t];
            for (int o = 0; o < 128; o++) s += Wimg[t*128+o] * bimgc[o];
            g_bc[t] = s;
        }
    }
}

// ---------------- merged x + A/C projection ----------------
__global__ void k_xAC(const float* __restrict__ opc, const float* __restrict__ W_in,
                      const float* __restrict__ b_in)
{
    int bn = blockIdx.x, o = threadIdx.x;  // 128
    __shared__ float xs[TD];
    __shared__ float p[3];
    if (o < 3) p[o] = opc[(size_t)bn*3 + o];
    __syncthreads();
    if (o < TD) {
        float v = __fadd_rn(__fadd_rn(__fadd_rn(__fmul_rn(p[0], W_in[o*3+0]),
                            __fmul_rn(p[1], W_in[o*3+1])), __fmul_rn(p[2], W_in[o*3+2])), b_in[o]);
        xs[o] = v;
    }
    __syncthreads();
    float a = 0.f, c2 = 0.f;
    #pragma unroll 8
    for (int c = 0; c < TD; c++) {
        float xv = xs[c];
        a  += xv * g_wgT[c*128 + o];
        c2 += xv * g_wgT[(c+TD)*128 + o];
    }
    g_A[(size_t)bn*GD + o] = a;
    g_C[(size_t)bn*GD + o] = c2 - a;
}

__global__ __launch_bounds__(128) void k_knn(const float* __restrict__ opc)
{
    __shared__ float sbuf[4*NN];
    float* sx  = sbuf;
    float* sy  = sbuf + NN;
    float* sz  = sbuf + 2*NN;
    float* ssq = sbuf + 3*NN;

    int b  = blockIdx.x >> 9;
    int nb = (blockIdx.x & 511) * 4;
    int t = threadIdx.x, w = t >> 5, lane = t & 31;
    const float* pcb = opc + (size_t)b*NN*3;
    for (int i = t; i < NN; i += 128) {
        float x = pcb[i*3+0], y = pcb[i*3+1], zz = pcb[i*3+2];
        sx[i] = x; sy[i] = y; sz[i] = zz;
        float s01 = __fadd_rn(__fmul_rn(x,x), __fmul_rn(y,y));
        ssq[i] = __fadd_rn(s01, __fmul_rn(zz,zz));
    }
    __syncthreads();

    int n = nb + w;
    float qx = sx[n], qy = sy[n], qz = sz[n], qsq = ssq[n];

    float d[KNN]; int id[KNN];
    #pragma unroll
    for (int j = 0; j < KNN; j++){ d[j] = FLT_MAX; id[j] = 0x7fffffff; }
    float worst = FLT_MAX; int wpos = 0;

    for (int m = lane; m < NN; m += 32) {
        float dot  = __fadd_rn(__fadd_rn(__fmul_rn(qx, sx[m]), __fmul_rn(qy, sy[m])),
                               __fmul_rn(qz, sz[m]));
        float dist = __fsub_rn(__fadd_rn(qsq, ssq[m]), __fmul_rn(2.0f, dot));
        if (dist < worst) {
            #pragma unroll
            for (int j = 0; j < KNN; j++) if (j == wpos){ d[j] = dist; id[j] = m; }
            worst = -FLT_MAX;
            #pragma unroll
            for (int j = 0; j < KNN; j++) if (d[j] > worst){ worst = d[j]; wpos = j; }
        }
    }
    __syncthreads();

    float* cd  = sbuf;
    int*   cid = (int*)(sbuf + 2560);
    int base = w*640 + lane*KNN;
    #pragma unroll
    for (int j = 0; j < KNN; j++){ cd[base+j] = d[j]; cid[base+j] = id[j]; }
    __syncwarp();

    int* out = g_idx + ((size_t)(b*NN + n))*KNN;
    for (int r = 0; r < KNN; r++) {
        float mv = FLT_MAX; int mp = 0; int midx = 0x7fffffff;
        #pragma unroll
        for (int j = 0; j < KNN; j++) {
            float v = cd[w*640 + lane*KNN + j];
            int   ii = cid[w*640 + lane*KNN + j];
            if (v < mv || (v == mv && ii < midx)) { mv = v; midx = ii; mp = lane*KNN + j; }
        }
        for (int off = 16; off; off >>= 1) {
            float ov = __shfl_down_sync(0xffffffffu, mv, off);
            int   oi = __shfl_down_sync(0xffffffffu, midx, off);
            int   op = __shfl_down_sync(0xffffffffu, mp, off);
            if (ov < mv || (ov == mv && oi < midx)) { mv = ov; midx = oi; mp = op; }
        }
        mp = __shfl_sync(0xffffffffu, mp, 0);
        if (lane == 0) { out[r] = cid[w*640 + mp]; cd[w*640 + mp] = FLT_MAX; }
        __syncwarp();
    }
}

__global__ void k_stats()
{
    int bn = blockIdx.x, b = bn >> 11, o = threadIdx.x;
    __shared__ int sidx[KNN];
    if (o < KNN) sidx[o] = g_idx[(size_t)bn*KNN + o];
    __syncthreads();
    float c = g_C[(size_t)bn*GD + o];
    const float* Ab = g_A + (size_t)b*NN*GD;
    float s1 = 0.f, s2 = 0.f;
    #pragma unroll
    for (int k = 0; k < KNN; k++) {
        float v = Ab[(size_t)sidx[k]*GD + o] + c;
        s1 += v; s2 += v*v;
    }
    for (int off = 16; off; off >>= 1) {
        s1 += __shfl_down_sync(0xffffffffu, s1, off);
        s2 += __shfl_down_sync(0xffffffffu, s2, off);
    }
    if ((o & 31) == 0) {
        int g = o >> 5;
        atomicAdd(&g_stats[(b*4+g)*2+0], (double)s1);
        atomicAdd(&g_stats[(b*4+g)*2+1], (double)s2);
    }
}

// finstats folded: each block recomputes mu/iv from g_stats (bit-identical math)
__global__ void k_f2(const float* __restrict__ gn_g, const float* __restrict__ gn_b,
                     const float* __restrict__ b_proj)
{
    __shared__ float fsh[16][GD];
    __shared__ int   sidx[16*KNN];
    __shared__ float smu[4], siv[4];
    int bn0 = blockIdx.x * 16;
    int b   = bn0 >> 11;
    int o   = threadIdx.x;
    int g   = o >> 5;
    if (o < 4) {
        double cnt = (double)NN * KNN * 32.0;
        double mu = g_stats[(b*4+o)*2+0] / cnt;
        double var = g_stats[(b*4+o)*2+1] / cnt - mu*mu;
        smu[o] = (float)mu;
        siv[o] = rsqrtf(__fadd_rn((float)var, EPSF));
    }
    for (int i = o; i < 16*KNN; i += 128) sidx[i] = g_idx[(size_t)bn0*KNN + i];
    __syncthreads();
    float mu = smu[g], iv = siv[g];
    float gg = gn_g[o], gb = gn_b[o];
    const float* Ab = g_A + (size_t)b*NN*GD;
    for (int p = 0; p < 16; p++) {
        float c = g_C[(size_t)(bn0+p)*GD + o];
        float m = -FLT_MAX;
        #pragma unroll
        for (int k = 0; k < KNN; k++) {
            float v = Ab[(size_t)sidx[p*KNN+k]*GD + o] + c;
            v = __fadd_rn(__fmul_rn(__fmul_rn(__fsub_rn(v, mu), iv), gg), gb);
            v = (v >= 0.f) ? v : __fmul_rn(0.2f, v);
            m = fmaxf(m, v);
        }
        fsh[p][o] = m;
    }
    __syncthreads();
    float acc[16];
    float bp = b_proj[o];
    #pragma unroll
    for (int p = 0; p < 16; p++) acc[p] = bp;
    for (int c = 0; c < GD; c++) {
        float wv = g_wpT[c*128 + o];
        #pragma unroll
        for (int p = 0; p < 16; p++) acc[p] += fsh[p][c] * wv;
    }
    for (int p = 0; p < 16; p++) g_f2[(size_t)(bn0+p)*GD + o] = acc[p];
}

__global__ void k_grid(const float* __restrict__ pc)
{
    int b = blockIdx.x, t = threadIdx.x;
    __shared__ float r[4][256];
    __shared__ float sp[3];
    const float* p = pc + (size_t)b*NN*3;

    float mnx = FLT_MAX, mny = FLT_MAX, mxx = -FLT_MAX, mxy = -FLT_MAX;
    for (int i = t; i < NN; i += 256) {
        float x = p[i*3], y = p[i*3+1];
        mnx = fminf(mnx,x); mxx = fmaxf(mxx,x);
        mny = fminf(mny,y); mxy = fmaxf(mxy,y);
    }
    r[0][t]=mnx; r[1][t]=mxx; r[2][t]=mny; r[3][t]=mxy;
    __syncthreads();
    for (int s = 128; s; s >>= 1) {
        if (t < s) {
            r[0][t]=fminf(r[0][t],r[0][t+s]); r[1][t]=fmaxf(r[1][t],r[1][t+s]);
            r[2][t]=fminf(r[2][t],r[2][t+s]); r[3][t]=fmaxf(r[3][t],r[3][t+s]);
        }
        __syncthreads();
    }
    if (t == 0) {
        float ex = __fsub_rn(r[1][0], r[0][0]);
        float ey = __fsub_rn(r[3][0], r[2][0]);
        float gs = divfull(fmaxf(ex, ey), 197.0f);
        g_bp[b*8+0] = r[0][0];
        g_bp[b*8+1] = r[2][0];
        g_bp[b*8+2] = gs;
        sp[0] = r[0][0]; sp[1] = r[2][0]; sp[2] = gs;
    }
    __syncthreads();
    float pmx = sp[0], pmy = sp[1], gs = sp[2];

    mnx = FLT_MAX; mny = FLT_MAX; mxx = -FLT_MAX; mxy = -FLT_MAX;
    for (int i = t; i < NN; i += 256) {
        float ix = floorf(divfull(__fsub_rn(p[i*3],   pmx), gs));
        float iy = floorf(divfull(__fsub_rn(p[i*3+1], pmy), gs));
        mnx = fminf(mnx,ix); mxx = fmaxf(mxx,ix);
        mny = fminf(mny,iy); mxy = fmaxf(mxy,iy);
    }
    __syncthreads();
    r[0][t]=mnx; r[1][t]=mxx; r[2][t]=mny; r[3][t]=mxy;
    __syncthreads();
    for (int s = 128; s; s >>= 1) {
        if (t < s) {
            r[0][t]=fminf(r[0][t],r[0][t+s]); r[1][t]=fmaxf(r[1][t],r[1][t+s]);
            r[2][t]=fminf(r[2][t],r[2][t+s]); r[3][t]=fmaxf(r[3][t],r[3][t+s]);
        }
        __syncthreads();
    }
    if (t == 0) {
        float cx = floorf(__fmul_rn(__fadd_rn(__fadd_rn(r[1][0], 2.0f), r[0][0]), 0.5f));
        float cy = floorf(__fmul_rn(__fadd_rn(__fadd_rn(r[3][0], 2.0f), r[2][0]), 0.5f));
        g_bp[b*8+3] = (float)OBJ*0.5f - cx - 1.0f;
        g_bp[b*8+4] = (float)OBJ*0.5f - cy - 1.0f;
    }
}

__global__ void k_scatter(const float* __restrict__ pc)
{
    int bn = blockIdx.x, b = bn >> 11, o = threadIdx.x;
    float pmx = g_bp[b*8+0], pmy = g_bp[b*8+1], gs = g_bp[b*8+2];
    float shx = g_bp[b*8+3], shy = g_bp[b*8+4];
    float x = pc[(size_t)bn*3], y = pc[(size_t)bn*3+1];
    float ix = floorf(divfull(__fsub_rn(x, pmx), gs));
    float iy = floorf(divfull(__fsub_rn(y, pmy), gs));
    float val = g_f2[(size_t)bn*GD + o];
    float bx = ix + 1.0f + shx, by = iy + 1.0f + shy;
    #pragma unroll
    for (int ox = -1; ox <= 1; ox++)
    #pragma unroll
    for (int oy = -1; oy <= 1; oy++) {
        int lin = (int)(__fadd_rn(__fmul_rn(bx + (float)ox, 200.0f), by + (float)oy));
        if (lin >= 0 && lin < OBJ*OBJ) {
            int gx = lin / OBJ, gy = lin - gx*OBJ;
            atomicAdd(&g_res[(((size_t)b*GD + o)*IMGD + gx + 12)*IMGD + gy + 12], val);
        }
    }
}

// ---------------- fp32 -> fp16 copy of g_res (conv1 input; rounding identical to pack) ----------------
__global__ void k_cvt()
{
    size_t i = (size_t)blockIdx.x*blockDim.x + threadIdx.x;
    size_t n4 = ((size_t)BB*GD*HW)/4;
    const float4* src = (const float4*)g_res;
    uint2* dst = (uint2*)g_resh;
    for (size_t j = i; j < n4; j += (size_t)gridDim.x*blockDim.x) {
        float4 v = src[j];
        __half2 h0 = __floats2half2_rn(v.x, v.y);
        __half2 h1 = __floats2half2_rn(v.z, v.w);
        dst[j] = make_uint2(*(unsigned*)&h0, *(unsigned*)&h1);
    }
}

// ---------------- FP16 tensor-core conv; variant1 fuses image head (atomic-free) ----------------
__global__ __launch_bounds__(256, 2) void k_conv_mma(int variant, float* __restrict__ outimg)
{
    const __half* in    = variant ? g_h1h : g_resh;
    const __half* wt    = variant ? g_w2h : g_w1h;
    const float*  bias  = variant ? g_b2  : g_b1;
    __half*       outh  = g_h1h;

    __shared__ unsigned sA2[2][128][9];   // [buf][px][kpair]
    __shared__ unsigned sB2[2][128][9];   // [buf][oc][kpair]
    __shared__ float hpart[2][3][128];    // [ocHalf][c][px] — single writer per slot
    __shared__ float swc[3*GD];

    int b = blockIdx.z;
    int pbase = blockIdx.x * 128;
    int t = threadIdx.x;             // 256
    int warp = t >> 5, lane = t & 31;
    int grp = lane >> 2, tid4 = lane & 3;
    int px0w = (warp & 3) * 32;
    int oc0w = (warp >> 2) * 64;

    int px = t & 127;                // fill: pixel
    int kh = t >> 7;                 // fill: k-half (0/1)
    int p_t = pbase + px;
    int row_t = p_t / IMGD;
    int col_t = p_t - row_t*IMGD;

    if (variant) {
        for (int i = t; i < 3*GD; i += 256) swc[i] = g_wc[i];
    }

    float acc[2][8][4];
    #pragma unroll
    for (int mt = 0; mt < 2; mt++)
        #pragma unroll
        for (int nt = 0; nt < 8; nt++)
            #pragma unroll
            for (int r = 0; r < 4; r++) acc[mt][nt][r] = 0.f;

    const __half* inb = in + (size_t)b*GD*HW;

    __half raf[8];
    uint4 rbv;

    #pragma unroll
    for (int j = 0; j < 8; j++) {
        int k = kh*8 + j;
        int ci = k / 9;
        int r  = k - ci*9;
        int dh = r/3 - 1, dw = r - (r/3)*3 - 1;
        int ih = row_t + dh, iw = col_t + dw;
        __half v = __ushort_as_half((unsigned short)0);
        if ((unsigned)ih < (unsigned)IMGD && (unsigned)iw < (unsigned)IMGD)
            v = inb[(size_t)ci*HW + ih*IMGD + iw];
        raf[j] = v;
    }
    rbv = ((const uint4*)(wt + (size_t)px*16))[kh];
    #pragma unroll
    for (int j = 0; j < 4; j++) {
        __half2 h = __halves2half2(raf[2*j], raf[2*j+1]);
        sA2[0][px][kh*4 + j] = *(unsigned*)&h;
    }
    sB2[0][px][kh*4+0]=rbv.x; sB2[0][px][kh*4+1]=rbv.y;
    sB2[0][px][kh*4+2]=rbv.z; sB2[0][px][kh*4+3]=rbv.w;
    __syncthreads();

    for (int i = 0; i < 72; i++) {
        int cur = i & 1;
        if (i < 71) {
            int kbase = (i + 1) * 16;
            #pragma unroll
            for (int j = 0; j < 8; j++) {
                int k = kbase + kh*8 + j;
                int ci = k / 9;
                int r  = k - ci*9;
                int dh = r/3 - 1, dw = r - (r/3)*3 - 1;
                int ih = row_t + dh, iw = col_t + dw;
                __half v = __ushort_as_half((unsigned short)0);
                if ((unsigned)ih < (unsigned)IMGD && (unsigned)iw < (unsigned)IMGD)
                    v = inb[(size_t)ci*HW + ih*IMGD + iw];
                raf[j] = v;
            }
            rbv = ((const uint4*)(wt + ((size_t)(i+1)*128 + px)*16))[kh];
        }

        {
            unsigned bfr[8][2];
            #pragma unroll
            for (int nt = 0; nt < 8; nt++) {
                int col = oc0w + nt*8 + grp;
                bfr[nt][0] = sB2[cur][col][tid4];
                bfr[nt][1] = sB2[cur][col][tid4 + 4];
            }
            #pragma unroll
            for (int mt = 0; mt < 2; mt++) {
                int r0 = px0w + mt*16 + grp;
                unsigned a0 = sA2[cur][r0    ][tid4];
                unsigned a1 = sA2[cur][r0 + 8][tid4];
                unsigned a2 = sA2[cur][r0    ][tid4 + 4];
                unsigned a3 = sA2[cur][r0 + 8][tid4 + 4];
                #pragma unroll
                for (int nt = 0; nt < 8; nt++) {
                    asm volatile(
                        "mma.sync.aligned.m16n8k16.row.col.f32.f16.f16.f32 "
                        "{%0,%1,%2,%3}, {%4,%5,%6,%7}, {%8,%9}, {%0,%1,%2,%3};"
                        : "+f"(acc[mt][nt][0]), "+f"(acc[mt][nt][1]),
                          "+f"(acc[mt][nt][2]), "+f"(acc[mt][nt][3])
                        : "r"(a0), "r"(a1), "r"(a2), "r"(a3),
                          "r"(bfr[nt][0]), "r"(bfr[nt][1]));
                }
            }
        }

        if (i < 71) {
            int nxt = cur ^ 1;
            #pragma unroll
            for (int j = 0; j < 4; j++) {
                __half2 h = __halves2half2(raf[2*j], raf[2*j+1]);
                sA2[nxt][px][kh*4 + j] = *(unsigned*)&h;
            }
            sB2[nxt][px][kh*4+0]=rbv.x; sB2[nxt][px][kh*4+1]=rbv.y;
            sB2[nxt][px][kh*4+2]=rbv.z; sB2[nxt][px][kh*4+3]=rbv.w;
        }
        __syncthreads();
    }

    if (!variant) {
        // conv1 epilogue: bias + relu -> h1 (fp16; identical to fp16 pack downstream)
        #pragma unroll
        for (int mt = 0; mt < 2; mt++) {
            int pxl = px0w + mt*16 + grp;
            #pragma unroll
            for (int nt = 0; nt < 8; nt++) {
                int oc = oc0w + nt*8 + tid4*2;
                float bv0 = bias[oc], bv1 = bias[oc+1];
                size_t base0 = ((size_t)b*GD + oc    )*HW + pbase;
                size_t base1 = ((size_t)b*GD + oc + 1)*HW + pbase;
                outh[base0 + pxl    ] = __float2half_rn(fmaxf(acc[mt][nt][0] + bv0, 0.f));
                outh[base1 + pxl    ] = __float2half_rn(fmaxf(acc[mt][nt][1] + bv1, 0.f));
                outh[base0 + pxl + 8] = __float2half_rn(fmaxf(acc[mt][nt][2] + bv0, 0.f));
                outh[base1 + pxl + 8] = __float2half_rn(fmaxf(acc[mt][nt][3] + bv1, 0.f));
            }
        }
    } else {
        // conv2 epilogue: h = relu(bn2+res); fused head, atomic-free
        const float* resid = g_res;
        float hp[2][2][3];
        #pragma unroll
        for (int mt = 0; mt < 2; mt++)
            #pragma unroll
            for (int q = 0; q < 2; q++)
                #pragma unroll
                for (int c = 0; c < 3; c++) hp[mt][q][c] = 0.f;

        #pragma unroll
        for (int mt = 0; mt < 2; mt++) {
            int pxl = px0w + mt*16 + grp;
            #pragma unroll
            for (int nt = 0; nt < 8; nt++) {
                int oc = oc0w + nt*8 + tid4*2;
                float bv0 = bias[oc], bv1 = bias[oc+1];
                size_t base0 = ((size_t)b*GD + oc    )*HW + pbase;
                size_t base1 = ((size_t)b*GD + oc + 1)*HW + pbase;
                float v00 = fmaxf(__fadd_rn(acc[mt][nt][0] + bv0, resid[base0 + pxl]), 0.f);
                float v01 = fmaxf(__fadd_rn(acc[mt][nt][1] + bv1, resid[base1 + pxl]), 0.f);
                float v10 = fmaxf(__fadd_rn(acc[mt][nt][2] + bv0, resid[base0 + pxl + 8]), 0.f);
                float v11 = fmaxf(__fadd_rn(acc[mt][nt][3] + bv1, resid[base1 + pxl + 8]), 0.f);
                #pragma unroll
                for (int c = 0; c < 3; c++) {
                    float w0 = swc[c*GD + oc], w1 = swc[c*GD + oc + 1];
                    hp[mt][0][c] += w0*v00 + w1*v01;
                    hp[mt][1][c] += w0*v10 + w1*v11;
                }
            }
        }
        // reduce over tid4 (lane bits 0-1)
        #pragma unroll
        for (int mt = 0; mt < 2; mt++)
            #pragma unroll
            for (int q = 0; q < 2; q++)
                #pragma unroll
                for (int c = 0; c < 3; c++) {
                    float v = hp[mt][q][c];
                    v += __shfl_xor_sync(0xffffffffu, v, 1);
                    v += __shfl_xor_sync(0xffffffffu, v, 2);
                    hp[mt][q][c] = v;
                }
        int ocHalf = warp >> 2;
        if (tid4 == 0) {
            #pragma unroll
            for (int mt = 0; mt < 2; mt++) {
                int pxl = px0w + mt*16 + grp;
                #pragma unroll
                for (int c = 0; c < 3; c++) {
                    hpart[ocHalf][c][pxl    ] = hp[mt][0][c];
                    hpart[ocHalf][c][pxl + 8] = hp[mt][1][c];
                }
            }
        }
        __syncthreads();
        if (t < 128) {
            int p2 = pbase + t;
            #pragma unroll
            for (int c = 0; c < 3; c++) {
                float s = __fadd_rn(__fadd_rn(hpart[0][c][t], hpart[1][c][t]), g_bc[c]);
                float ii = __fdiv_rn(1.f, __fadd_rn(1.f, expf(-s)));
                const float sub[3] = {0.485f, 0.456f, 0.406f};
                const float den[3] = {0.229f, 0.224f, 0.225f};
                outimg[((size_t)b*3 + c)*HW + p2] = __fdiv_rn(__fsub_rn(ii, sub[c]), den[c]);
            }
        }
    }
}

extern "C" void kernel_launch(void* const* d_in, const int* in_sizes, int n_in,
                              void* d_out, int out_size)
{
    const float* opc    = (const float*)d_in[0];
    const float* pc     = (const float*)d_in[1];
    const float* W_in   = (const float*)d_in[2];
    const float* b_in   = (const float*)d_in[3];
    const float* Wg     = (const float*)d_in[4];
    const float* gn_g   = (const float*)d_in[5];
    const float* gn_b   = (const float*)d_in[6];
    const float* Wp     = (const float*)d_in[7];
    const float* b_proj = (const float*)d_in[8];
    const float* W1     = (const float*)d_in[9];
    const float* bn1g   = (const float*)d_in[10];
    const float* bn1b   = (const float*)d_in[11];
    const float* bn1m   = (const float*)d_in[12];
    const float* bn1v   = (const float*)d_in[13];
    const float* W2     = (const float*)d_in[14];
    const float* bn2g   = (const float*)d_in[15];
    const float* bn2b   = (const float*)d_in[16];
    const float* bn2m   = (const float*)d_in[17];
    const float* bn2v   = (const float*)d_in[18];
    const float* Wimgc  = (const float*)d_in[19];
    const float* bimgc  = (const float*)d_in[20];
    const float* Wimg   = (const float*)d_in[21];
    const float* bimg   = (const float*)d_in[22];
    float* out = (float*)d_out;

    k_init<<<4096, 256>>>(W1, bn1g, bn1b, bn1m, bn1v,
                          W2, bn2g, bn2b, bn2m, bn2v,
                          Wg, Wp, Wimgc, bimgc, Wimg, bimg);

    k_xAC<<<BB*NN, 128>>>(opc, W_in, b_in);
    k_knn<<<BB*NN/4, 128>>>(opc);
    k_stats<<<BB*NN, 128>>>();
    k_f2<<<BB*NN/16, 128>>>(gn_g, gn_b, b_proj);

    k_grid<<<BB, 256>>>(pc);
    k_scatter<<<BB*NN, 128>>>(pc);
    k_cvt<<<2048, 256>>>();

    dim3 cgrid(HW/128, 1, BB);
    k_conv_mma<<<cgrid, 256>>>(0, out);
    k_conv_mma<<<cgrid, 256>>>(1, out);
}